// round 17
// baseline (speedup 1.0000x reference)
#include <cuda_runtime.h>
#include <cuda_fp16.h>
#include <cstdint>

// Problem dims
#define M_DIM 16384
#define N_DIM 4096
#define K_DIM 256
#define NQ    31

// Fragment-layout scratch (one MMA operand per lane, 512B blocks = 32 lanes x 16B)
// X': [mblk 1024][kblk 32]  kblk = c*4 + h*2 + sub   (h: 0=hi 1=lo)   16 MB fp16
// W': [nblk 256][kblk 16]   kblk = c*2 + sub         (single fp16)     2 MB
__device__ uint4 g_Xf[1024 * 32 * 32];
__device__ uint4 g_Wf[256 * 16 * 32];

// GEMM tiling: CTA 128x128, 8 warps 4(m) x 2(n), warp tile 32x64
#define BM 128
#define BN 128
#define NCHUNK 8

// ---- dynamic smem layout (bytes) ----
#define OFF_QS   0                    // 128 x 33 f32 = 16896
#define OFF_BB   16896                // 128 f32     = 512
#define OFF_ST   17408                // 8 warps x 16 x 64 f32 = 32768
#define SMEM_BYTES 50176

__device__ __forceinline__ void ldg128(uint32_t* r, const uint4* p) {
    asm volatile("ld.global.nc.v4.u32 {%0,%1,%2,%3}, [%4];"
                 : "=r"(r[0]), "=r"(r[1]), "=r"(r[2]), "=r"(r[3]) : "l"(p));
}
__device__ __forceinline__ void mma16816(float* d, const uint32_t* a, const uint32_t* b) {
    asm volatile(
        "mma.sync.aligned.m16n8k16.row.col.f32.f16.f16.f32 "
        "{%0,%1,%2,%3}, {%4,%5,%6,%7}, {%8,%9}, {%0,%1,%2,%3};"
        : "+f"(d[0]), "+f"(d[1]), "+f"(d[2]), "+f"(d[3])
        : "r"(a[0]), "r"(a[1]), "r"(a[2]), "r"(a[3]), "r"(b[0]), "r"(b[1]));
}
__device__ __forceinline__ void splitx2(float2 v, uint32_t& hi, uint32_t& lo) {
    __half h0 = __float2half_rn(v.x);
    __half h1 = __float2half_rn(v.y);
    __half2 H(h0, h1);
    __half2 L(__float2half_rn(v.x - __half2float(h0)),
              __float2half_rn(v.y - __half2float(h1)));
    hi = *(uint32_t*)&H;
    lo = *(uint32_t*)&L;
}
__device__ __forceinline__ uint32_t pack2(float2 v) {
    __half2 H(__float2half_rn(v.x), __float2half_rn(v.y));
    return *(uint32_t*)&H;
}

// ============ kernel 1: fp32 -> fp16 fragments =====
// A-reg order : r0=(g,c0) r1=(g+8,c0) r2=(g,c0+8) r3=(g+8,c0+8)
// B-reg order : r0=(g,c0) r1=(g,c0+8) r2=(g+8,c0) r3=(g+8,c0+8)
__global__ void __launch_bounds__(256)
convert_kernel(const float* __restrict__ X, const float* __restrict__ W)
{
    int t = blockIdx.x * blockDim.x + threadIdx.x;   // 655360 total
    const int lane = t & 31;
    const int g  = lane >> 2;
    const int c0 = (lane & 3) * 2;
    int rest = t >> 5;
    const int sub = rest & 1;
    const int c   = (rest >> 1) & 7;
    int blk = rest >> 4;

    if (blk < 1024) {   // X: hi + lo
        const float* src = X + (size_t)(blk * 16 + g) * K_DIM + c * 32 + sub * 16 + c0;
        float2 v0 = *(const float2*)(src);
        float2 v2 = *(const float2*)(src + 8);
        float2 v1 = *(const float2*)(src + 8 * K_DIM);
        float2 v3 = *(const float2*)(src + 8 * K_DIM + 8);
        uint32_t h0, l0, h1, l1, h2, l2, h3, l3;
        splitx2(v0, h0, l0); splitx2(v1, h1, l1);
        splitx2(v2, h2, l2); splitx2(v3, h3, l3);
        uint4* dst = g_Xf + ((size_t)blk * 32 + c * 4 + sub) * 32 + lane;
        dst[0]      = make_uint4(h0, h1, h2, h3);   // hi
        dst[2 * 32] = make_uint4(l0, l1, l2, l3);   // lo
    } else {            // W: single fp16
        blk -= 1024;
        const float* src = W + (size_t)(blk * 16 + g) * K_DIM + c * 32 + sub * 16 + c0;
        float2 v0 = *(const float2*)(src);
        float2 v2 = *(const float2*)(src + 8);
        float2 v1 = *(const float2*)(src + 8 * K_DIM);
        float2 v3 = *(const float2*)(src + 8 * K_DIM + 8);
        uint4* dst = g_Wf + ((size_t)blk * 16 + c * 2 + sub) * 32 + lane;
        dst[0] = make_uint4(pack2(v0), pack2(v2), pack2(v1), pack2(v3));
    }
}

// ============ kernel 2: barrier-free HMMA GEMM + transposed-store epilogue ===
extern __shared__ char smem[];

__global__ void __launch_bounds__(256, 2)
gemm_kernel(const float* __restrict__ bias, const float* __restrict__ Q,
            float* __restrict__ out, float* __restrict__ idxf)
{
    const int tid  = threadIdx.x;
    const int wid  = tid >> 5;
    const int lane = tid & 31;
    const int bm = blockIdx.y * BM;
    const int bn = blockIdx.x * BN;

    const int wm = wid >> 1;
    const int wn = wid & 1;
    const int g  = lane >> 2;
    const int t4 = lane & 3;

    float* qs = (float*)(smem + OFF_QS);
    float* bb = (float*)(smem + OFF_BB);
    float* stg = (float*)(smem + OFF_ST) + wid * (16 * 64);   // per-warp 16x64

    // A stream: mblk stride 32 kblk * 32 lanes = 1024; B stream: nblk stride 512
    const uint4* pA0 = g_Xf + ((size_t)(bm >> 4) + wm * 2) * 1024 + lane;
    const uint4* pA1 = pA0 + 1024;
    const uint4* pB0 = g_Wf + ((size_t)(bn >> 4) + wn * 4) * 512 + lane;
    const uint4* pB1 = pB0 + 512;
    const uint4* pB2 = pB1 + 512;
    const uint4* pB3 = pB2 + 512;

    float acc[2][8][4];
    #pragma unroll
    for (int im = 0; im < 2; im++)
        #pragma unroll
        for (int in = 0; in < 8; in++)
            #pragma unroll
            for (int r = 0; r < 4; r++) acc[im][in][r] = 0.f;

    uint32_t A0[2][2][4], A1[2][2][4], B[4][4];

#define LOAD_A(Abuf, off)                      \
    do {                                       \
        ldg128(Abuf[0][0], pA0 + (off));       \
        ldg128(Abuf[1][0], pA0 + (off) + 64);  \
        ldg128(Abuf[0][1], pA1 + (off));       \
        ldg128(Abuf[1][1], pA1 + (off) + 64);  \
    } while (0)

#define DO_MMAS(Abuf)                                            \
    do {                                                         \
        _Pragma("unroll")                                        \
        for (int nb = 0; nb < 4; nb++) {                         \
            _Pragma("unroll")                                    \
            for (int im = 0; im < 2; im++) {                     \
                _Pragma("unroll")                                \
                for (int half = 0; half < 2; half++) {           \
                    float* d = acc[im][nb * 2 + half];           \
                    mma16816(d, Abuf[0][im], B[nb] + half * 2);  \
                    mma16816(d, Abuf[1][im], B[nb] + half * 2);  \
                }                                                \
            }                                                    \
        }                                                        \
    } while (0)

    LOAD_A(A0, 0);

    for (int c = 0; c < NCHUNK; ++c) {
        const int ca = c * 128;
        const int cb = c * 64;

        ldg128(B[0], pB0 + cb);
        ldg128(B[1], pB1 + cb);
        ldg128(B[2], pB2 + cb);
        ldg128(B[3], pB3 + cb);
        LOAD_A(A1, ca + 32);
        DO_MMAS(A0);

        ldg128(B[0], pB0 + cb + 32);
        ldg128(B[1], pB1 + cb + 32);
        ldg128(B[2], pB2 + cb + 32);
        ldg128(B[3], pB3 + cb + 32);
        if (c + 1 < NCHUNK) LOAD_A(A0, ca + 128);
        DO_MMAS(A1);
    }
#undef LOAD_A
#undef DO_MMAS

    // ---- stage quantiles + bias ----
    for (int i = tid; i < BN * NQ; i += 256) {
        int n = i / NQ, r = i - n * NQ;
        qs[n * 33 + r] = Q[(size_t)(bn + n) * NQ + r];
    }
    if (tid < BN) bb[tid] = bias[bn + tid];
    __syncthreads();

    // ---- epilogue: per-warp smem transpose -> fully packed STG.128 ----
    // staging layout: stg[row*64 + (col ^ ((row&7)*8))], row 0..15, col 0..63
    const int r2  = lane >> 4;          // readback: row parity
    const int cb4 = (lane & 15) * 4;    // readback: col block

    #pragma unroll
    for (int arr = 0; arr < 2; arr++) {          // 0: out+bias, 1: indices
        float* dst = arr ? idxf : out;
        #pragma unroll
        for (int im = 0; im < 2; im++) {
            __syncwarp();                        // buffer reuse (WAR across lanes)
            // scatter phase: STS.64 per (in, half)
            #pragma unroll
            for (int in = 0; in < 8; in++) {
                const int col_c = wn * 64 + in * 8 + t4 * 2;   // CTA-local col
                const int cw = in * 8 + t4 * 2;                // warp-local col
                #pragma unroll
                for (int half = 0; half < 2; half++) {
                    const int rw = g + half * 8;               // warp-local row
                    const float v0 = acc[im][in][half * 2];
                    const float v1 = acc[im][in][half * 2 + 1];
                    float s0, s1;
                    if (arr == 0) {
                        s0 = v0 + bb[col_c];
                        s1 = v1 + bb[col_c + 1];
                    } else {
                        const float* q0 = qs + col_c * 33;
                        const float* q1 = q0 + 33;
                        int p0 = 0, p1 = 0;
                        if (q0[15]     < v0) p0 = 16;
                        if (q0[p0 + 7] < v0) p0 += 8;
                        if (q0[p0 + 3] < v0) p0 += 4;
                        if (q0[p0 + 1] < v0) p0 += 2;
                        if (q0[p0]     < v0) p0 += 1;
                        if (q1[15]     < v1) p1 = 16;
                        if (q1[p1 + 7] < v1) p1 += 8;
                        if (q1[p1 + 3] < v1) p1 += 4;
                        if (q1[p1 + 1] < v1) p1 += 2;
                        if (q1[p1]     < v1) p1 += 1;
                        s0 = (float)p0;
                        s1 = (float)p1;
                    }
                    *(float2*)&stg[rw * 64 + (cw ^ ((rw & 7) * 8))] = make_float2(s0, s1);
                }
            }
            __syncwarp();
            // gather phase: LDS.128 row-major -> STG.128 (512B fully packed)
            #pragma unroll
            for (int rr = 0; rr < 16; rr += 2) {
                const int rw = rr + r2;
                float4 v = *(float4*)&stg[rw * 64 + (cb4 ^ ((rw & 7) * 8))];
                const size_t off = (size_t)(bm + wm * 32 + im * 16 + rw) * N_DIM
                                 + bn + wn * 64 + cb4;
                *(float4*)(dst + off) = v;
            }
        }
    }
}

// ================= launch =================
extern "C" void kernel_launch(void* const* d_in, const int* in_sizes, int n_in,
                              void* d_out, int out_size)
{
    const float* x    = (const float*)d_in[0];  // [16384, 256]
    const float* w    = (const float*)d_in[1];  // [4096, 256]
    const float* bias = (const float*)d_in[2];  // [4096]
    const float* q    = (const float*)d_in[3];  // [4096, 31]

    float* out  = (float*)d_out;
    float* idxf = out + (size_t)M_DIM * N_DIM;

    cudaFuncSetAttribute(gemm_kernel, cudaFuncAttributeMaxDynamicSharedMemorySize, SMEM_BYTES);

    convert_kernel<<<655360 / 256, 256>>>(x, w);
    dim3 grid(N_DIM / BN, M_DIM / BM);   // (32, 128) = 4096 blocks
    gemm_kernel<<<grid, 256, SMEM_BYTES>>>(bias, q, out, idxf);
}